// round 15
// baseline (speedup 1.0000x reference)
#include <cuda_runtime.h>
#include <cstdint>

#define LAYERS 8
#define EPS_F 1e-7f

typedef unsigned long long ull;

__device__ __forceinline__ ull pack2(float x, float y) {
    ull r; asm("mov.b64 %0, {%1, %2};" : "=l"(r) : "f"(x), "f"(y)); return r;
}
__device__ __forceinline__ void unpack2(ull v, float& x, float& y) {
    asm("mov.b64 {%0, %1}, %2;" : "=f"(x), "=f"(y) : "l"(v));
}
__device__ __forceinline__ ull fma2(ull a, ull b, ull c) {
    ull d; asm("fma.rn.f32x2 %0, %1, %2, %3;" : "=l"(d) : "l"(a), "l"(b), "l"(c)); return d;
}

// Duplicated quadratic-form coefficients, one row j of circuit q:
// [ (C0,C0,C1,C1), (C2,C2,C3,C3), (C4,C4,C5,C5), (C6,C6,C7,C7), (C8,C8,0,0) ]
// p_j(x) = (1,u0,v0) C^j (1,u1,v1)^T, u0=cos x, v0=sin x,
//          u1=cos(pi x/2), v1=sin(pi x/2).
__device__ float4 g_Cd4[3][4][5];

// ---------------------------------------------------------------------------
// Pre-kernel: 1 block, 3 warps (one per circuit), cooperative build of C^j.
// ---------------------------------------------------------------------------
__global__ void qmdn_pre(const float* __restrict__ wp,
                         const float* __restrict__ wm,
                         const float* __restrict__ ws) {
    __shared__ float sR[3][LAYERS][2][2][2][2];
    __shared__ float sP[3][LAYERS][4][4][2];
    __shared__ float sM[3][4][4][2];

    int wid  = threadIdx.x >> 5;
    int lane = threadIdx.x & 31;
    if (wid >= 3) return;
    int q = wid;
    const float* w = (q == 0) ? wp : (q == 1) ? wm : ws;

    if (lane < 16) {   // 16 Rot gates in parallel (lane = 2*layer + wire)
        int l = lane >> 1, wi = lane & 1;
        float phi = w[(l * 2 + wi) * 3 + 0];
        float th  = w[(l * 2 + wi) * 3 + 1];
        float om  = w[(l * 2 + wi) * 3 + 2];
        float st, ct, sapo, capo, samo, camo;
        __sincosf(0.5f * th, &st, &ct);
        __sincosf(0.5f * (phi + om), &sapo, &capo);
        __sincosf(0.5f * (phi - om), &samo, &camo);
        sR[q][l][wi][0][0][0] =  capo * ct;  sR[q][l][wi][0][0][1] = -sapo * ct;
        sR[q][l][wi][0][1][0] = -camo * st;  sR[q][l][wi][0][1][1] = -samo * st;
        sR[q][l][wi][1][0][0] =  camo * st;  sR[q][l][wi][1][0][1] = -samo * st;
        sR[q][l][wi][1][1][0] =  capo * ct;  sR[q][l][wi][1][1][1] =  sapo * ct;
    }
    __syncwarp();

    if (lane < 16) {   // per-layer row-permuted Kronecker
        int r = lane >> 2, c = lane & 3;
        const int src[4] = {0, 2, 3, 1};
        int rs = src[r], i0 = rs >> 1, j0 = rs & 1, i1 = c >> 1, j1 = c & 1;
#pragma unroll
        for (int l = 0; l < LAYERS; l++) {
            float ar = sR[q][l][0][i0][i1][0], ai = sR[q][l][0][i0][i1][1];
            float br = sR[q][l][1][j0][j1][0], bi = sR[q][l][1][j0][j1][1];
            sP[q][l][r][c][0] = ar * br - ai * bi;
            sP[q][l][r][c][1] = ar * bi + ai * br;
        }
    }
    __syncwarp();

    for (int np = 4; np >= 1; np >>= 1) {   // log-tree product U = PK7..PK0
        float res[4][2];
        if (lane < 16) {
            int r = lane >> 2, c = lane & 3;
            for (int m = 0; m < np; m++) {
                float sr = 0.f, si = 0.f;
#pragma unroll
                for (int k = 0; k < 4; k++) {
                    float ar = sP[q][2 * m + 1][r][k][0], ai = sP[q][2 * m + 1][r][k][1];
                    float br = sP[q][2 * m][k][c][0],     bi = sP[q][2 * m][k][c][1];
                    sr += ar * br - ai * bi;
                    si += ar * bi + ai * br;
                }
                res[m][0] = sr; res[m][1] = si;
            }
        }
        __syncwarp();
        if (lane < 16) {
            int r = lane >> 2, c = lane & 3;
            for (int m = 0; m < np; m++) {
                sP[q][m][r][c][0] = res[m][0];
                sP[q][m][r][c][1] = res[m][1];
            }
        }
        __syncwarp();
    }

    if (lane < 16) {   // fold column phases {1,-i,-i,-1}
        int r = lane >> 2, c = lane & 3;
        float ur = sP[q][0][r][c][0], ui = sP[q][0][r][c][1];
        float mr, mi;
        if (c == 0)      { mr =  ur; mi =  ui; }
        else if (c == 3) { mr = -ur; mi = -ui; }
        else             { mr =  ui; mi = -ur; }   // -i*(a+bi) = b - ai
        sM[q][r][c][0] = mr;
        sM[q][r][c][1] = mi;
    }
    __syncwarp();

    if (lane < 4) {    // build C^j, write duplicated-pack layout to global
        int j = lane;
        float mr[4], mi[4];
#pragma unroll
        for (int k = 0; k < 4; k++) { mr[k] = sM[q][j][k][0]; mi[k] = sM[q][j][k][1]; }
        const float bas[3][3] = { {0.5f,  0.5f, 0.f},
                                  {0.f,   0.f,  0.5f},
                                  {0.5f, -0.5f, 0.f} };
        float C[9] = {0,0,0,0,0,0,0,0,0};
#pragma unroll
        for (int k = 0; k < 4; k++)
#pragma unroll
            for (int l = 0; l < 4; l++) {
                float Q = mr[k] * mr[l] + mi[k] * mi[l];   // Re(z_k conj(z_l))
                int a0 = (k >> 1) + (l >> 1);
                int b1 = (k & 1) + (l & 1);
#pragma unroll
                for (int al = 0; al < 3; al++)
#pragma unroll
                    for (int be = 0; be < 3; be++)
                        C[al * 3 + be] += Q * bas[a0][al] * bas[b1][be];
            }
        g_Cd4[q][j][0] = make_float4(C[0], C[0], C[1], C[1]);
        g_Cd4[q][j][1] = make_float4(C[2], C[2], C[3], C[3]);
        g_Cd4[q][j][2] = make_float4(C[4], C[4], C[5], C[5]);
        g_Cd4[q][j][3] = make_float4(C[6], C[6], C[7], C[7]);
        g_Cd4[q][j][4] = make_float4(C[8], C[8], 0.f, 0.f);
    }
}

// ---------------------------------------------------------------------------
// Main kernel: 4 elems/thread as 2 packed pairs; quad-form rows via fma.rn.f32x2
// with duplicated coefficients. No smem, no barrier.
// out: [pi (B,3) | mu (B,3) | sigma (B,3)] row-major.
// ---------------------------------------------------------------------------
__global__ void __launch_bounds__(256, 3)
qmdn_main(const float4* __restrict__ x4, float* __restrict__ out, int B) {
    int nGroups = B >> 2;
    int t = blockIdx.x * blockDim.x + threadIdx.x;
    if (t >= nGroups) return;

    const float CLIP_LO = EPS_F;
    const float CLIP_HI = 1.0f - EPS_F;
    const float LN2 = 0.69314718056f;
    size_t regionStride = 3 * (size_t)B;

    float4 xv = x4[t];
    float xs[4] = {xv.x, xv.y, xv.z, xv.w};
    float u0[4], v0[4], u1[4], v1[4];
#pragma unroll
    for (int e = 0; e < 4; e++) {
        __sincosf(xs[e], &v0[e], &u0[e]);
        __sincosf(1.5707963267948966f * xs[e], &v1[e], &u1[e]);
    }
    // pair-packed trig: [h] = (elem 2h, elem 2h+1)
    ull u0p[2], v0p[2], u1p[2], v1p[2];
#pragma unroll
    for (int h = 0; h < 2; h++) {
        u0p[h] = pack2(u0[2*h], u0[2*h+1]);
        v0p[h] = pack2(v0[2*h], v0[2*h+1]);
        u1p[h] = pack2(u1[2*h], u1[2*h+1]);
        v1p[h] = pack2(v1[2*h], v1[2*h+1]);
    }

#pragma unroll
    for (int q = 0; q < 3; q++) {
        int nrows = (q == 0) ? 3 : 4;
        ull P[2][4];   // packed probs [pair][row]
#pragma unroll
        for (int j = 0; j < 4; j++) {
            if (j >= nrows) break;
            float4 f0 = __ldg(&g_Cd4[q][j][0]);   // (C0,C0,C1,C1)
            float4 f1 = __ldg(&g_Cd4[q][j][1]);   // (C2,C2,C3,C3)
            float4 f2 = __ldg(&g_Cd4[q][j][2]);   // (C4,C4,C5,C5)
            float4 f3 = __ldg(&g_Cd4[q][j][3]);   // (C6,C6,C7,C7)
            float4 f4 = __ldg(&g_Cd4[q][j][4]);   // (C8,C8, -, -)
            ull c0d = pack2(f0.x, f0.y), c1d = pack2(f0.z, f0.w);
            ull c2d = pack2(f1.x, f1.y), c3d = pack2(f1.z, f1.w);
            ull c4d = pack2(f2.x, f2.y), c5d = pack2(f2.z, f2.w);
            ull c6d = pack2(f3.x, f3.y), c7d = pack2(f3.z, f3.w);
            ull c8d = pack2(f4.x, f4.y);
#pragma unroll
            for (int h = 0; h < 2; h++) {
                ull w0 = fma2(v1p[h], c2d, fma2(u1p[h], c1d, c0d));
                ull w1 = fma2(v1p[h], c5d, fma2(u1p[h], c4d, c3d));
                ull w2 = fma2(v1p[h], c8d, fma2(u1p[h], c7d, c6d));
                P[h][j] = fma2(v0p[h], w2, fma2(u0p[h], w1, w0));
            }
        }

        float* base = out + q * regionStride + (size_t)t * 12;
#pragma unroll
        for (int h = 0; h < 2; h++) {
            float pa[4], pb[4];
#pragma unroll
            for (int j = 0; j < 4; j++) {
                if (j >= nrows) break;
                unpack2(P[h][j], pa[j], pb[j]);
            }
            float o0, o1, o2, o3, o4, o5;
            if (q == 0) {
                float ia = __fdividef(1.0f, pa[0] + pa[1] + pa[2]);
                float ib = __fdividef(1.0f, pb[0] + pb[1] + pb[2]);
                o0 = pa[0] * ia; o1 = pa[1] * ia; o2 = pa[2] * ia;
                o3 = pb[0] * ib; o4 = pb[1] * ib; o5 = pb[2] * ib;
            } else {
#pragma unroll
                for (int j = 0; j < 4; j++) {
                    pa[j] = fminf(fmaxf(pa[j], CLIP_LO), CLIP_HI);
                    pb[j] = fminf(fmaxf(pb[j], CLIP_LO), CLIP_HI);
                }
                if (q == 1) {
                    float la3 = __log2f(pa[3]), lb3 = __log2f(pb[3]);
                    o0 = (__log2f(pa[0]) - la3) * LN2;
                    o1 = (__log2f(pa[1]) - la3) * LN2;
                    o2 = (__log2f(pa[2]) - la3) * LN2;
                    o3 = (__log2f(pb[0]) - lb3) * LN2;
                    o4 = (__log2f(pb[1]) - lb3) * LN2;
                    o5 = (__log2f(pb[2]) - lb3) * LN2;
                } else {
                    float ia = __fdividef(1.0f, pa[3]);
                    float ib = __fdividef(1.0f, pb[3]);
                    o0 = pa[0] * ia; o1 = pa[1] * ia; o2 = pa[2] * ia;
                    o3 = pb[0] * ib; o4 = pb[1] * ib; o5 = pb[2] * ib;
                }
            }
            float2* d2 = (float2*)(base + h * 6);
            d2[0] = make_float2(o0, o1);
            d2[1] = make_float2(o2, o3);
            d2[2] = make_float2(o4, o5);
        }
    }
}

extern "C" void kernel_launch(void* const* d_in, const int* in_sizes, int n_in,
                              void* d_out, int out_size) {
    const float* x  = (const float*)d_in[0];
    const float* wp = (const float*)d_in[1];
    const float* wm = (const float*)d_in[2];
    const float* ws = (const float*)d_in[3];
    float* out = (float*)d_out;
    int B = in_sizes[0];

    qmdn_pre<<<1, 96>>>(wp, wm, ws);

    int nGroups = B >> 2;
    int threads = 256;
    int blocks = (nGroups + threads - 1) / threads;   // 1024 @ B=2^20
    qmdn_main<<<blocks, threads>>>((const float4*)x, out, B);
}

// round 16
// speedup vs baseline: 1.6286x; 1.6286x over previous
#include <cuda_runtime.h>
#include <cstdint>

#define LAYERS 8
#define EPS_F 1e-7f

// Folded circuit matrices (column phases {1,-i,-i,-1} folded in):
// g_M4 = 3 circuits x 4x4 complex = 96 floats = 24 float4.
// Layout: [q][row][col][re/im] flattened.
__device__ float4 g_M4[24];

// ---------------------------------------------------------------------------
// Pre-kernel: 1 block, 3 warps (one per circuit), cooperative build of M'.
// ---------------------------------------------------------------------------
__global__ void qmdn_pre(const float* __restrict__ wp,
                         const float* __restrict__ wm,
                         const float* __restrict__ ws) {
    __shared__ float sR[3][LAYERS][2][2][2][2];
    __shared__ float sP[3][LAYERS][4][4][2];

    int wid  = threadIdx.x >> 5;
    int lane = threadIdx.x & 31;
    if (wid >= 3) return;
    int q = wid;
    const float* w = (q == 0) ? wp : (q == 1) ? wm : ws;

    if (lane < 16) {   // 16 Rot gates in parallel (lane = 2*layer + wire)
        int l = lane >> 1, wi = lane & 1;
        float phi = w[(l * 2 + wi) * 3 + 0];
        float th  = w[(l * 2 + wi) * 3 + 1];
        float om  = w[(l * 2 + wi) * 3 + 2];
        float st, ct, sapo, capo, samo, camo;
        __sincosf(0.5f * th, &st, &ct);
        __sincosf(0.5f * (phi + om), &sapo, &capo);
        __sincosf(0.5f * (phi - om), &samo, &camo);
        sR[q][l][wi][0][0][0] =  capo * ct;  sR[q][l][wi][0][0][1] = -sapo * ct;
        sR[q][l][wi][0][1][0] = -camo * st;  sR[q][l][wi][0][1][1] = -samo * st;
        sR[q][l][wi][1][0][0] =  camo * st;  sR[q][l][wi][1][0][1] = -samo * st;
        sR[q][l][wi][1][1][0] =  capo * ct;  sR[q][l][wi][1][1][1] =  sapo * ct;
    }
    __syncwarp();

    if (lane < 16) {   // per-layer row-permuted Kronecker
        int r = lane >> 2, c = lane & 3;
        const int src[4] = {0, 2, 3, 1};
        int rs = src[r], i0 = rs >> 1, j0 = rs & 1, i1 = c >> 1, j1 = c & 1;
#pragma unroll
        for (int l = 0; l < LAYERS; l++) {
            float ar = sR[q][l][0][i0][i1][0], ai = sR[q][l][0][i0][i1][1];
            float br = sR[q][l][1][j0][j1][0], bi = sR[q][l][1][j0][j1][1];
            sP[q][l][r][c][0] = ar * br - ai * bi;
            sP[q][l][r][c][1] = ar * bi + ai * br;
        }
    }
    __syncwarp();

    for (int np = 4; np >= 1; np >>= 1) {   // log-tree product U = PK7..PK0
        float res[4][2];
        if (lane < 16) {
            int r = lane >> 2, c = lane & 3;
            for (int m = 0; m < np; m++) {
                float sr = 0.f, si = 0.f;
#pragma unroll
                for (int k = 0; k < 4; k++) {
                    float ar = sP[q][2 * m + 1][r][k][0], ai = sP[q][2 * m + 1][r][k][1];
                    float br = sP[q][2 * m][k][c][0],     bi = sP[q][2 * m][k][c][1];
                    sr += ar * br - ai * bi;
                    si += ar * bi + ai * br;
                }
                res[m][0] = sr; res[m][1] = si;
            }
        }
        __syncwarp();
        if (lane < 16) {
            int r = lane >> 2, c = lane & 3;
            for (int m = 0; m < np; m++) {
                sP[q][m][r][c][0] = res[m][0];
                sP[q][m][r][c][1] = res[m][1];
            }
        }
        __syncwarp();
    }

    if (lane < 16) {   // fold column phases {1,-i,-i,-1}, write to global
        int r = lane >> 2, c = lane & 3;
        float ur = sP[q][0][r][c][0], ui = sP[q][0][r][c][1];
        float mr, mi;
        if (c == 0)      { mr =  ur; mi =  ui; }
        else if (c == 3) { mr = -ur; mi = -ui; }
        else             { mr =  ui; mi = -ur; }   // -i*(a+bi) = b - ai
        // flat index: q*32 + r*8 + c*2 (+0 re, +1 im); write as scalar floats
        float* gm = (float*)g_M4;
        gm[q * 32 + r * 8 + c * 2 + 0] = mr;
        gm[q * 32 + r * 8 + c * 2 + 1] = mi;
    }
}

// ---------------------------------------------------------------------------
// Main kernel: R1-style. Stage 96 floats to smem (24 float4 copy), then
// 4 elems/thread complex mat-vec, elems outer, rows inner, pi skips row 3.
// out layout: [pi (B,3) | mu (B,3) | sigma (B,3)], row-major.
// ---------------------------------------------------------------------------
__global__ void __launch_bounds__(256, 4)
qmdn_main(const float4* __restrict__ x4, float* __restrict__ out, int B) {
    __shared__ float sM[3][4][4][2];    // [q][row][col][re/im]
    int tid = threadIdx.x;
    if (tid < 24) ((float4*)sM)[tid] = g_M4[tid];
    __syncthreads();

    int nGroups = B >> 2;
    int t = blockIdx.x * blockDim.x + tid;
    if (t >= nGroups) return;

    const float CLIP_LO = EPS_F;
    const float CLIP_HI = 1.0f - EPS_F;
    size_t regionStride = 3 * (size_t)B;

    float4 xv = x4[t];
    float xs[4] = {xv.x, xv.y, xv.z, xv.w};

    float a[4][4];
#pragma unroll
    for (int e = 0; e < 4; e++) {
        float s0, c0, s1, c1;
        __sincosf(0.5f * xs[e], &s0, &c0);
        __sincosf(0.78539816339744831f * xs[e], &s1, &c1);
        a[e][0] = c0 * c1; a[e][1] = c0 * s1;
        a[e][2] = s0 * c1; a[e][3] = s0 * s1;
    }

#pragma unroll
    for (int q = 0; q < 3; q++) {
        float o[12];
#pragma unroll
        for (int e = 0; e < 4; e++) {
            float p[4];
            int nrows = (q == 0) ? 3 : 4;     // pi never uses p[3]
#pragma unroll
            for (int j = 0; j < 4; j++) {
                if (j >= nrows) break;
                float re = 0.f, im = 0.f;
#pragma unroll
                for (int k = 0; k < 4; k++) {
                    re = fmaf(sM[q][j][k][0], a[e][k], re);
                    im = fmaf(sM[q][j][k][1], a[e][k], im);
                }
                p[j] = fmaf(re, re, im * im);
            }
            if (q == 0) {
                float inv = __fdividef(1.0f, p[0] + p[1] + p[2]);
                o[e * 3 + 0] = p[0] * inv;
                o[e * 3 + 1] = p[1] * inv;
                o[e * 3 + 2] = p[2] * inv;
            } else {
                float pc[4];
#pragma unroll
                for (int j = 0; j < 4; j++)
                    pc[j] = fminf(fmaxf(p[j], CLIP_LO), CLIP_HI);
                if (q == 1) {
                    float l3 = __logf(pc[3]);
                    o[e * 3 + 0] = __logf(pc[0]) - l3;
                    o[e * 3 + 1] = __logf(pc[1]) - l3;
                    o[e * 3 + 2] = __logf(pc[2]) - l3;
                } else {
                    float inv = __fdividef(1.0f, pc[3]);
                    o[e * 3 + 0] = pc[0] * inv;
                    o[e * 3 + 1] = pc[1] * inv;
                    o[e * 3 + 2] = pc[2] * inv;
                }
            }
        }
        float4* dst = (float4*)(out + q * regionStride + (size_t)t * 12);
        dst[0] = make_float4(o[0], o[1], o[2],  o[3]);
        dst[1] = make_float4(o[4], o[5], o[6],  o[7]);
        dst[2] = make_float4(o[8], o[9], o[10], o[11]);
    }
}

extern "C" void kernel_launch(void* const* d_in, const int* in_sizes, int n_in,
                              void* d_out, int out_size) {
    const float* x  = (const float*)d_in[0];
    const float* wp = (const float*)d_in[1];
    const float* wm = (const float*)d_in[2];
    const float* ws = (const float*)d_in[3];
    float* out = (float*)d_out;
    int B = in_sizes[0];

    qmdn_pre<<<1, 96>>>(wp, wm, ws);

    int nGroups = B >> 2;
    int threads = 256;
    int blocks = (nGroups + threads - 1) / threads;   // 1024 @ B=2^20
    qmdn_main<<<blocks, threads>>>((const float4*)x, out, B);
}

// round 17
// speedup vs baseline: 1.6827x; 1.0332x over previous
#include <cuda_runtime.h>
#include <cstdint>

#define LAYERS 8
#define EPS_F 1e-7f

// Folded circuit matrices (column phases {1,-i,-i,-1} folded in):
// 3 circuits x 4x4 complex = 96 floats = 24 float4. [q][row][col][re/im].
__device__ float4 g_M4[24];

// ---------------------------------------------------------------------------
// Pre-kernel: 1 block, 3 warps (one per circuit), cooperative build of M'.
// ---------------------------------------------------------------------------
__global__ void qmdn_pre(const float* __restrict__ wp,
                         const float* __restrict__ wm,
                         const float* __restrict__ ws) {
    __shared__ float sR[3][LAYERS][2][2][2][2];
    __shared__ float sP[3][LAYERS][4][4][2];

    int wid  = threadIdx.x >> 5;
    int lane = threadIdx.x & 31;
    if (wid >= 3) return;
    int q = wid;
    const float* w = (q == 0) ? wp : (q == 1) ? wm : ws;

    if (lane < 16) {   // 16 Rot gates in parallel (lane = 2*layer + wire)
        int l = lane >> 1, wi = lane & 1;
        float phi = w[(l * 2 + wi) * 3 + 0];
        float th  = w[(l * 2 + wi) * 3 + 1];
        float om  = w[(l * 2 + wi) * 3 + 2];
        float st, ct, sapo, capo, samo, camo;
        __sincosf(0.5f * th, &st, &ct);
        __sincosf(0.5f * (phi + om), &sapo, &capo);
        __sincosf(0.5f * (phi - om), &samo, &camo);
        sR[q][l][wi][0][0][0] =  capo * ct;  sR[q][l][wi][0][0][1] = -sapo * ct;
        sR[q][l][wi][0][1][0] = -camo * st;  sR[q][l][wi][0][1][1] = -samo * st;
        sR[q][l][wi][1][0][0] =  camo * st;  sR[q][l][wi][1][0][1] = -samo * st;
        sR[q][l][wi][1][1][0] =  capo * ct;  sR[q][l][wi][1][1][1] =  sapo * ct;
    }
    __syncwarp();

    if (lane < 16) {   // per-layer row-permuted Kronecker
        int r = lane >> 2, c = lane & 3;
        const int src[4] = {0, 2, 3, 1};
        int rs = src[r], i0 = rs >> 1, j0 = rs & 1, i1 = c >> 1, j1 = c & 1;
#pragma unroll
        for (int l = 0; l < LAYERS; l++) {
            float ar = sR[q][l][0][i0][i1][0], ai = sR[q][l][0][i0][i1][1];
            float br = sR[q][l][1][j0][j1][0], bi = sR[q][l][1][j0][j1][1];
            sP[q][l][r][c][0] = ar * br - ai * bi;
            sP[q][l][r][c][1] = ar * bi + ai * br;
        }
    }
    __syncwarp();

    for (int np = 4; np >= 1; np >>= 1) {   // log-tree product U = PK7..PK0
        float res[4][2];
        if (lane < 16) {
            int r = lane >> 2, c = lane & 3;
            for (int m = 0; m < np; m++) {
                float sr = 0.f, si = 0.f;
#pragma unroll
                for (int k = 0; k < 4; k++) {
                    float ar = sP[q][2 * m + 1][r][k][0], ai = sP[q][2 * m + 1][r][k][1];
                    float br = sP[q][2 * m][k][c][0],     bi = sP[q][2 * m][k][c][1];
                    sr += ar * br - ai * bi;
                    si += ar * bi + ai * br;
                }
                res[m][0] = sr; res[m][1] = si;
            }
        }
        __syncwarp();
        if (lane < 16) {
            int r = lane >> 2, c = lane & 3;
            for (int m = 0; m < np; m++) {
                sP[q][m][r][c][0] = res[m][0];
                sP[q][m][r][c][1] = res[m][1];
            }
        }
        __syncwarp();
    }

    if (lane < 16) {   // fold column phases {1,-i,-i,-1}, write to global
        int r = lane >> 2, c = lane & 3;
        float ur = sP[q][0][r][c][0], ui = sP[q][0][r][c][1];
        float mr, mi;
        if (c == 0)      { mr =  ur; mi =  ui; }
        else if (c == 3) { mr = -ur; mi = -ui; }
        else             { mr =  ui; mi = -ur; }   // -i*(a+bi) = b - ai
        float* gm = (float*)g_M4;
        gm[q * 32 + r * 8 + c * 2 + 0] = mr;
        gm[q * 32 + r * 8 + c * 2 + 1] = mi;
    }
}

// ---------------------------------------------------------------------------
// Main kernel (PDL secondary): preamble (x load + trig) BEFORE
// griddepcontrol.wait, then stage g_M4 -> smem and compute.
// out layout: [pi (B,3) | mu (B,3) | sigma (B,3)], row-major.
// ---------------------------------------------------------------------------
__global__ void __launch_bounds__(256, 4)
qmdn_main(const float4* __restrict__ x4, float* __restrict__ out, int B) {
    __shared__ float sM[3][4][4][2];    // [q][row][col][re/im]
    int tid = threadIdx.x;
    int nGroups = B >> 2;
    int t = blockIdx.x * blockDim.x + tid;
    bool active = (t < nGroups);

    // -------- independent preamble: overlaps with the pre-kernel --------
    float4 xv = active ? x4[t] : make_float4(0.f, 0.f, 0.f, 0.f);
    float xs[4] = {xv.x, xv.y, xv.z, xv.w};
    float a[4][4];
#pragma unroll
    for (int e = 0; e < 4; e++) {
        float s0, c0, s1, c1;
        __sincosf(0.5f * xs[e], &s0, &c0);
        __sincosf(0.78539816339744831f * xs[e], &s1, &c1);
        a[e][0] = c0 * c1; a[e][1] = c0 * s1;
        a[e][2] = s0 * c1; a[e][3] = s0 * s1;
    }

    // -------- wait for pre-kernel completion (PDL) --------
    asm volatile("griddepcontrol.wait;" ::: "memory");

    if (tid < 24) ((float4*)sM)[tid] = g_M4[tid];
    __syncthreads();
    if (!active) return;

    const float CLIP_LO = EPS_F;
    const float CLIP_HI = 1.0f - EPS_F;
    size_t regionStride = 3 * (size_t)B;

#pragma unroll
    for (int q = 0; q < 3; q++) {
        float o[12];
#pragma unroll
        for (int e = 0; e < 4; e++) {
            float p[4];
            int nrows = (q == 0) ? 3 : 4;     // pi never uses p[3]
#pragma unroll
            for (int j = 0; j < 4; j++) {
                if (j >= nrows) break;
                float re = 0.f, im = 0.f;
#pragma unroll
                for (int k = 0; k < 4; k++) {
                    re = fmaf(sM[q][j][k][0], a[e][k], re);
                    im = fmaf(sM[q][j][k][1], a[e][k], im);
                }
                p[j] = fmaf(re, re, im * im);
            }
            if (q == 0) {
                float inv = __fdividef(1.0f, p[0] + p[1] + p[2]);
                o[e * 3 + 0] = p[0] * inv;
                o[e * 3 + 1] = p[1] * inv;
                o[e * 3 + 2] = p[2] * inv;
            } else {
                float pc[4];
#pragma unroll
                for (int j = 0; j < 4; j++)
                    pc[j] = fminf(fmaxf(p[j], CLIP_LO), CLIP_HI);
                if (q == 1) {
                    float l3 = __logf(pc[3]);
                    o[e * 3 + 0] = __logf(pc[0]) - l3;
                    o[e * 3 + 1] = __logf(pc[1]) - l3;
                    o[e * 3 + 2] = __logf(pc[2]) - l3;
                } else {
                    float inv = __fdividef(1.0f, pc[3]);
                    o[e * 3 + 0] = pc[0] * inv;
                    o[e * 3 + 1] = pc[1] * inv;
                    o[e * 3 + 2] = pc[2] * inv;
                }
            }
        }
        float4* dst = (float4*)(out + q * regionStride + (size_t)t * 12);
        dst[0] = make_float4(o[0], o[1], o[2],  o[3]);
        dst[1] = make_float4(o[4], o[5], o[6],  o[7]);
        dst[2] = make_float4(o[8], o[9], o[10], o[11]);
    }
}

extern "C" void kernel_launch(void* const* d_in, const int* in_sizes, int n_in,
                              void* d_out, int out_size) {
    const float* x  = (const float*)d_in[0];
    const float* wp = (const float*)d_in[1];
    const float* wm = (const float*)d_in[2];
    const float* ws = (const float*)d_in[3];
    float* out = (float*)d_out;
    int B = in_sizes[0];

    qmdn_pre<<<1, 96>>>(wp, wm, ws);

    int nGroups = B >> 2;
    int threads = 256;
    int blocks = (nGroups + threads - 1) / threads;   // 1024 @ B=2^20

    cudaLaunchConfig_t cfg = {};
    cfg.gridDim  = dim3((unsigned)blocks, 1, 1);
    cfg.blockDim = dim3((unsigned)threads, 1, 1);
    cudaLaunchAttribute attrs[1];
    attrs[0].id = cudaLaunchAttributeProgrammaticStreamSerialization;
    attrs[0].val.programmaticStreamSerializationAllowed = 1;
    cfg.attrs = attrs;
    cfg.numAttrs = 1;
    cudaLaunchKernelEx(&cfg, qmdn_main, (const float4*)x, out, B);
}